// round 12
// baseline (speedup 1.0000x reference)
#include <cuda_runtime.h>
#include <cstdint>

constexpr int Bc = 256;   // batch
constexpr int Cc = 128;   // channels
constexpr int Hc = 1024;  // hidden
constexpr int Ic = 512;   // input features
constexpr int Oc = 128;   // output features

constexpr int AWORDS = 256 * 20;            // A stage tile: 256 rows x (16+4) words
constexpr int BWORDS = 128 * 20;            // B stage tile
constexpr int STAGEW = AWORDS + BWORDS;     // 7680 words
constexpr int SMEM_BYTES = 4 * STAGEW * 4;  // 122880 B (4 stages)

// hidden activations scratch: [b][c][h]  (128 MB, static device global)
__device__ float g_h[(size_t)Bc * Cc * Hc];

__device__ __forceinline__ uint32_t s2u(const void* p) {
    uint32_t a;
    asm("{ .reg .u64 t; cvta.to.shared.u64 t, %1; cvt.u32.u64 %0, t; }" : "=r"(a) : "l"(p));
    return a;
}
__device__ __forceinline__ void cp16(uint32_t dst, const float* src) {
    asm volatile("cp.async.cg.shared.global [%0], [%1], 16;" :: "r"(dst), "l"(src));
}
__device__ __forceinline__ void mma8(float4& d,
                                     uint32_t a0, uint32_t a1, uint32_t a2, uint32_t a3,
                                     uint32_t b0, uint32_t b1) {
    asm volatile(
        "mma.sync.aligned.m16n8k8.row.col.f32.tf32.tf32.f32 "
        "{%0,%1,%2,%3}, {%4,%5,%6,%7}, {%8,%9}, {%0,%1,%2,%3};"
        : "+f"(d.x), "+f"(d.y), "+f"(d.z), "+f"(d.w)
        : "r"(a0), "r"(a1), "r"(a2), "r"(a3), "r"(b0), "r"(b1));
}
// fp32 bits -> tf32 round-to-nearest (HMMA drops low 13 bits; +0x1000 = RN)
__device__ __forceinline__ uint32_t rn(uint32_t u) { return u + 0x1000u; }

// ---------------------------------------------------------------------------
// 4-stage cp.async pipelined tf32 GEMM, 256x128 CTA tile, 512 threads,
// 16 warps each owning a 64x32 warp tile (acc[4][4] float4 = 64 regs).
// Loader (per stage, 3 cp16/thread, branch-free):
//   j0: A row tid>>2      koff (tid&3)*4
//   j1: A row (tid>>2)+128 same koff
//   j2: B row tid>>2      same koff
// ---------------------------------------------------------------------------
#define CP_STAGE(S)                                                              \
    do {                                                                         \
        const int _sl = (S) & 3;                                                 \
        const uint32_t _b = sbase + (uint32_t)(_sl * STAGEW) * 4;                \
        cp16(_b + dst0, src0 + (S) * 16);                                        \
        cp16(_b + dst1, src1 + (S) * 16);                                        \
        cp16(_b + dst2, src2 + (S) * 16);                                        \
    } while (0)

#define GEMM_MAINLOOP(KDIM)                                                      \
    float4 acc[4][4];                                                            \
    _Pragma("unroll") for (int t = 0; t < 4; t++)                                \
        _Pragma("unroll") for (int u = 0; u < 4; u++)                            \
            acc[t][u] = make_float4(0.f, 0.f, 0.f, 0.f);                         \
    const int NIT = (KDIM) / 16;                                                 \
    _Pragma("unroll") for (int s = 0; s < 3; s++) {                              \
        CP_STAGE(s);                                                             \
        asm volatile("cp.async.commit_group;" ::: "memory");                     \
    }                                                                            \
    for (int i = 0; i < NIT; i++) {                                              \
        const int sl = i & 3;                                                    \
        asm volatile("cp.async.wait_group 2;" ::: "memory");                     \
        __syncthreads();                                                         \
        if (i + 3 < NIT) CP_STAGE(i + 3);                                        \
        asm volatile("cp.async.commit_group;" ::: "memory");                     \
        const uint32_t* Afp = smw + sl * STAGEW + faoff;                         \
        const uint32_t* Bfp = smw + sl * STAGEW + AWORDS + fboff;                \
        _Pragma("unroll") for (int kk = 0; kk < 16; kk += 8) {                   \
            uint32_t a[4][4], b[4][2];                                           \
            _Pragma("unroll") for (int t = 0; t < 4; t++) {                      \
                a[t][0] = rn(Afp[(t * 16) * 20 + kk]);                           \
                a[t][1] = rn(Afp[(t * 16 + 8) * 20 + kk]);                       \
                a[t][2] = rn(Afp[(t * 16) * 20 + kk + 4]);                       \
                a[t][3] = rn(Afp[(t * 16 + 8) * 20 + kk + 4]);                   \
            }                                                                    \
            _Pragma("unroll") for (int u = 0; u < 4; u++) {                      \
                b[u][0] = rn(Bfp[(u * 8) * 20 + kk]);                            \
                b[u][1] = rn(Bfp[(u * 8) * 20 + kk + 4]);                        \
            }                                                                    \
            _Pragma("unroll") for (int t = 0; t < 4; t++)                        \
                _Pragma("unroll") for (int u = 0; u < 4; u++)                    \
                    mma8(acc[t][u], a[t][0], a[t][1], a[t][2], a[t][3],          \
                         b[u][0], b[u][1]);                                      \
        }                                                                        \
    }

// common per-thread index setup
#define COMMON_IDX                                                               \
    const int tid = threadIdx.x, l = tid & 31, w = tid >> 5;                     \
    const int wm = (w & 3) * 64, wn = (w >> 2) * 32;                             \
    const int lr4 = l >> 2, lc4 = l & 3;                                         \
    const int lrow = tid >> 2, lko = (tid & 3) * 4;                              \
    const int faoff = (wm + lr4) * 20 + lc4;                                     \
    const int fboff = (wn + lr4) * 20 + lc4;                                     \
    const uint32_t dst0 = (uint32_t)(lrow * 20 + lko) * 4;                       \
    const uint32_t dst1 = dst0 + (uint32_t)(128 * 20) * 4;                       \
    const uint32_t dst2 = (uint32_t)(AWORDS + lrow * 20 + lko) * 4;

// ---------------------------------------------------------------------------
// Kernel 1: h[b, c, :] = relu(X_c @ W1_c^T + b1_c)
//   M = 256 (all batch), N-tile = 128 of Hc. grid (8, 1, 128)
// ---------------------------------------------------------------------------
__global__ __launch_bounds__(512, 1)
void mlp_k1(const float* __restrict__ x, const float* __restrict__ w1,
            const float* __restrict__ b1) {
    extern __shared__ uint32_t smw[];
    const int c = blockIdx.z, n0 = blockIdx.x * 128;
    COMMON_IDX
    const uint32_t sbase = s2u(smw);

    const float* src0 = x  + ((size_t)lrow * Cc + c) * Ic + lko;          // A rows 0-127
    const float* src1 = src0 + (size_t)128 * Cc * Ic;                     // A rows 128-255
    const float* src2 = w1 + ((size_t)c * Hc + n0 + lrow) * Ic + lko;     // B rows

    GEMM_MAINLOOP(Ic)

    #pragma unroll
    for (int t = 0; t < 4; t++) {
        const int r0 = wm + t * 16 + lr4;
        #pragma unroll
        for (int u = 0; u < 4; u++) {
            const int n = n0 + wn + u * 8 + lc4 * 2;
            const float2 bb = *(const float2*)&b1[c * Hc + n];
            float2 lo = {fmaxf(acc[t][u].x + bb.x, 0.f),
                         fmaxf(acc[t][u].y + bb.y, 0.f)};
            float2 hi = {fmaxf(acc[t][u].z + bb.x, 0.f),
                         fmaxf(acc[t][u].w + bb.y, 0.f)};
            *(float2*)&g_h[((size_t)r0 * Cc + c) * Hc + n]       = lo;
            *(float2*)&g_h[((size_t)(r0 + 8) * Cc + c) * Hc + n] = hi;
        }
    }
}

// ---------------------------------------------------------------------------
// Kernel 2: out[b, :, c] = h[b, c, :] @ W2_c^T + b2_c   (output (B, O, C))
//   M = 256 (all batch), N = 128 = Oc. grid (1, 1, 128) -> single wave
// ---------------------------------------------------------------------------
__global__ __launch_bounds__(512, 1)
void mlp_k2(const float* __restrict__ w2, const float* __restrict__ b2,
            float* __restrict__ out) {
    extern __shared__ uint32_t smw[];
    const int c = blockIdx.z;
    COMMON_IDX
    const uint32_t sbase = s2u(smw);

    const float* src0 = g_h + ((size_t)lrow * Cc + c) * Hc + lko;         // A rows 0-127
    const float* src1 = src0 + (size_t)128 * Cc * Hc;                     // A rows 128-255
    const float* src2 = w2 + ((size_t)c * Oc + lrow) * Hc + lko;          // B rows

    GEMM_MAINLOOP(Hc)

    #pragma unroll
    for (int t = 0; t < 4; t++) {
        const int r0 = wm + t * 16 + lr4;
        #pragma unroll
        for (int u = 0; u < 4; u++) {
            const int n = wn + u * 8 + lc4 * 2;
            const float2 bb = *(const float2*)&b2[c * Oc + n];
            out[((size_t)r0 * Oc + n) * Cc + c]           = acc[t][u].x + bb.x;
            out[((size_t)r0 * Oc + n + 1) * Cc + c]       = acc[t][u].y + bb.y;
            out[((size_t)(r0 + 8) * Oc + n) * Cc + c]     = acc[t][u].z + bb.x;
            out[((size_t)(r0 + 8) * Oc + n + 1) * Cc + c] = acc[t][u].w + bb.y;
        }
    }
}

extern "C" void kernel_launch(void* const* d_in, const int* in_sizes, int n_in,
                              void* d_out, int out_size) {
    const float* x  = (const float*)d_in[0];
    const float* w1 = (const float*)d_in[1];
    const float* b1 = (const float*)d_in[2];
    const float* w2 = (const float*)d_in[3];
    const float* b2 = (const float*)d_in[4];
    float* out = (float*)d_out;

    static bool attr_set = false;
    if (!attr_set) {
        cudaFuncSetAttribute(mlp_k1, cudaFuncAttributeMaxDynamicSharedMemorySize, SMEM_BYTES);
        cudaFuncSetAttribute(mlp_k2, cudaFuncAttributeMaxDynamicSharedMemorySize, SMEM_BYTES);
        attr_set = true;
    }

    dim3 block(512);
    dim3 grid1(Hc / 128, 1, Cc);   // (8, 1, 128) = 1024 CTAs
    dim3 grid2(1,        1, Cc);   // (1, 1, 128) = 128 CTAs, single wave
    mlp_k1<<<grid1, block, SMEM_BYTES>>>(x, w1, b1);
    mlp_k2<<<grid2, block, SMEM_BYTES>>>(w2, b2, out);
}